// round 1
// baseline (speedup 1.0000x reference)
#include <cuda_runtime.h>
#include <cstdint>

// Problem constants
#define NS   4
#define NB   2
#define NF   64
#define NP   16
#define NHID 32
#define THW  131072            // 32*64*64
#define NPIX (NB * THW)        // 262144
#define OUT_ELEMS (NB * NF * THW)  // 16777216 floats, alpha follows

typedef unsigned long long u64;

__device__ __forceinline__ u64 pack2(float lo, float hi) {
    u64 r;
    asm("mov.b64 %0, {%1, %2};" : "=l"(r) : "f"(lo), "f"(hi));
    return r;
}
__device__ __forceinline__ void unpack2(u64 v, float& lo, float& hi) {
    asm("mov.b64 {%0, %1}, %2;" : "=f"(lo), "=f"(hi) : "l"(v));
}
__device__ __forceinline__ u64 fma2(u64 a, u64 b, u64 c) {
    u64 d;
    asm("fma.rn.f32x2 %0, %1, %2, %3;" : "=l"(d) : "l"(a), "l"(b), "l"(c));
    return d;
}
__device__ __forceinline__ u64 mul2(u64 a, u64 b) {
    u64 d;
    asm("mul.rn.f32x2 %0, %1, %2;" : "=l"(d) : "l"(a), "l"(b));
    return d;
}

// Column permutation: store o at col = (o%16)*2 + o/16 so the lane pair's
// two LDS.64 (o = i and o = 16+i) hit adjacent 8B slots -> conflict-free.
__device__ __forceinline__ int pcol(int o) { return ((o & 15) << 1) | (o >> 4); }

__global__ __launch_bounds__(128, 3) void gssm_kernel(
    const float* __restrict__ feats,   // (S,B,F,T,H,W)
    const float* __restrict__ ps,      // (B,P,T,H,W)
    const float* __restrict__ w1,      // (HID, F+P)
    const float* __restrict__ gamma,
    const float* __restrict__ beta,
    const float* __restrict__ mean,
    const float* __restrict__ var,
    const float* __restrict__ w2,      // (HID,)
    float* __restrict__ out)           // [OUT_ELEMS out][B*S*THW alpha]
{
    __shared__ u64 w1t2[80][32];       // {w,w} packed, permuted columns
    __shared__ u64 sc2[32], sh2[32];   // BN scale/shift packed, permuted
    __shared__ float w2s[32];          // unpermuted (scalar access, bank-safe)

    const int tid = threadIdx.x;

    // ---- stage weights / BN params in smem ----
    for (int idx = tid; idx < 80 * 32; idx += 128) {
        int k = idx >> 5, o = idx & 31;
        float w = w1[o * 80 + k];
        w1t2[k][pcol(o)] = pack2(w, w);
    }
    if (tid < 32) {
        int o = tid;
        float s  = gamma[o] / sqrtf(var[o] + 1e-5f);
        float sh = beta[o] - mean[o] * s;
        sc2[pcol(o)] = pack2(s, s);
        sh2[pcol(o)] = pack2(sh, sh);
        w2s[o] = w2[o];
    }
    __syncthreads();

    // ---- thread mapping: lane pair shares one pixel-pair, splits HID ----
    const int  ohalf = tid & 1;                       // 0: o in [0,16), 1: [16,32)
    const long gp    = (long)blockIdx.x * 64 + (tid >> 1);
    const long pix0  = gp * 2;                        // even -> 8B aligned
    const int  b     = (int)(pix0 >> 17);             // THW = 2^17
    const int  thw   = (int)(pix0 & (THW - 1));

    const u64* fsp0 = (const u64*)(feats + (((long)(0 * 2 + b)) << 23) + thw);
    const u64* fsp1 = (const u64*)(feats + (((long)(1 * 2 + b)) << 23) + thw);
    const u64* fsp2 = (const u64*)(feats + (((long)(2 * 2 + b)) << 23) + thw);
    const u64* fsp3 = (const u64*)(feats + (((long)(3 * 2 + b)) << 23) + thw);

    // ---- p-part (shared across all s) ----
    u64 acc[4][16];
#pragma unroll
    for (int i = 0; i < 16; i++) acc[0][i] = 0ULL;

    const u64* psp = (const u64*)(ps + (((long)b * NP) << 17) + thw);
#pragma unroll
    for (int p = 0; p < NP; p++) {
        u64 pv = psp[(long)p << 16];
#pragma unroll
        for (int i = 0; i < 16; i++)
            acc[0][i] = fma2(w1t2[64 + p][2 * i + ohalf], pv, acc[0][i]);
    }
#pragma unroll
    for (int i = 0; i < 16; i++) { acc[1][i] = acc[0][i]; acc[2][i] = acc[0][i]; acc[3][i] = acc[0][i]; }

    // ---- main GEMV over f: one weight LDS feeds 4 FMA2 (all s) ----
#pragma unroll 2
    for (int f = 0; f < NF; f++) {
        u64 v0 = fsp0[(long)f << 16];
        u64 v1 = fsp1[(long)f << 16];
        u64 v2 = fsp2[(long)f << 16];
        u64 v3 = fsp3[(long)f << 16];
#pragma unroll
        for (int i = 0; i < 16; i++) {
            u64 w = w1t2[f][2 * i + ohalf];
            acc[0][i] = fma2(w, v0, acc[0][i]);
            acc[1][i] = fma2(w, v1, acc[1][i]);
            acc[2][i] = fma2(w, v2, acc[2][i]);
            acc[3][i] = fma2(w, v3, acc[3][i]);
        }
    }

    // ---- BN + ReLU + logit dot, reduce across the lane pair ----
    float llo[4], lhi[4];
#pragma unroll
    for (int s = 0; s < 4; s++) {
        float alo = 0.f, ahi = 0.f;
#pragma unroll
        for (int i = 0; i < 16; i++) {
            u64 h = fma2(acc[s][i], sc2[2 * i + ohalf], sh2[2 * i + ohalf]);
            float x, y;
            unpack2(h, x, y);
            x = fmaxf(x, 0.f);
            y = fmaxf(y, 0.f);
            float wv = w2s[ohalf * 16 + i];
            alo = fmaf(wv, x, alo);
            ahi = fmaf(wv, y, ahi);
        }
        alo += __shfl_xor_sync(0xffffffffu, alo, 1);
        ahi += __shfl_xor_sync(0xffffffffu, ahi, 1);
        llo[s] = alo;
        lhi[s] = ahi;
    }

    // ---- softmax over s (b2 is a constant shift -> cancels) ----
    float mlo = fmaxf(fmaxf(llo[0], llo[1]), fmaxf(llo[2], llo[3]));
    float mhi = fmaxf(fmaxf(lhi[0], lhi[1]), fmaxf(lhi[2], lhi[3]));
    float elo[4], ehi[4], zlo = 0.f, zhi = 0.f;
#pragma unroll
    for (int s = 0; s < 4; s++) {
        elo[s] = __expf(llo[s] - mlo);  zlo += elo[s];
        ehi[s] = __expf(lhi[s] - mhi);  zhi += ehi[s];
    }
    float rlo = 1.f / zlo, rhi = 1.f / zhi;
    u64 a2[4];
#pragma unroll
    for (int s = 0; s < 4; s++) a2[s] = pack2(elo[s] * rlo, ehi[s] * rhi);

    // ---- alpha output: (B,S,T,H,W), even lane of each pair writes ----
    if (ohalf == 0) {
        u64* ap = (u64*)(out + OUT_ELEMS + (((long)b * NS) << 17) + thw);
#pragma unroll
        for (int s = 0; s < 4; s++) ap[(long)s << 16] = a2[s];
    }

    // ---- pass 2: out[f] = sum_s alpha_s * feats[s,f]; lane pair splits f ----
    u64* op = (u64*)(out + (((long)b) << 23) + thw);
    const int fbeg = ohalf * 32;
#pragma unroll 4
    for (int f = fbeg; f < fbeg + 32; f++) {
        u64 v = mul2(a2[0], fsp0[(long)f << 16]);
        v = fma2(a2[1], fsp1[(long)f << 16], v);
        v = fma2(a2[2], fsp2[(long)f << 16], v);
        v = fma2(a2[3], fsp3[(long)f << 16], v);
        op[(long)f << 16] = v;
    }
}

extern "C" void kernel_launch(void* const* d_in, const int* in_sizes, int n_in,
                              void* d_out, int out_size) {
    const float* feats = (const float*)d_in[0];
    const float* ps    = (const float*)d_in[1];
    const float* w1    = (const float*)d_in[2];
    const float* gamma = (const float*)d_in[3];
    const float* beta  = (const float*)d_in[4];
    const float* mean  = (const float*)d_in[5];
    const float* var   = (const float*)d_in[6];
    const float* w2    = (const float*)d_in[7];
    // d_in[8] = b2: constant logit shift, cancels in softmax
    float* out = (float*)d_out;

    const int blocks = NPIX / 128;  // 2048: 128 threads = 64 pixel-pairs each
    gssm_kernel<<<blocks, 128>>>(feats, ps, w1, gamma, beta, mean, var, w2, out);
}

// round 2
// speedup vs baseline: 1.0520x; 1.0520x over previous
#include <cuda_runtime.h>
#include <cstdint>

#define NS   4
#define NB   2
#define NF   64
#define NP   16
#define NHID 32
#define THW  131072            // 32*64*64 = 2^17
#define NPIX (NB * THW)        // 262144
#define OUT_ELEMS (NB * NF * THW)  // 16777216 floats; alpha follows

typedef unsigned long long u64;

__device__ __forceinline__ u64 pack2(float lo, float hi) {
    u64 r;
    asm("mov.b64 %0, {%1, %2};" : "=l"(r) : "f"(lo), "f"(hi));
    return r;
}
__device__ __forceinline__ void unpack2(u64 v, float& lo, float& hi) {
    asm("mov.b64 {%0, %1}, %2;" : "=f"(lo), "=f"(hi) : "l"(v));
}
__device__ __forceinline__ u64 fma2(u64 a, u64 b, u64 c) {
    u64 d;
    asm("fma.rn.f32x2 %0, %1, %2, %3;" : "=l"(d) : "l"(a), "l"(b), "l"(c));
    return d;
}
__device__ __forceinline__ u64 mul2(u64 a, u64 b) {
    u64 d;
    asm("mul.rn.f32x2 %0, %1, %2;" : "=l"(d) : "l"(a), "l"(b));
    return d;
}

// Column permutation: o at col = (o%8)*4 + o/8 so a 4-lane group's LDS.64
// addresses (o = i, 8+i, 16+i, 24+i) are 4 consecutive 8B slots -> conflict-free.
__device__ __forceinline__ int pcol(int o) { return ((o & 7) << 2) | (o >> 3); }

__global__ __launch_bounds__(128, 4) void gssm_kernel(
    const float* __restrict__ feats,   // (S,B,F,T,H,W)
    const float* __restrict__ ps,      // (B,P,T,H,W)
    const float* __restrict__ w1,      // (HID, F+P)
    const float* __restrict__ gamma,
    const float* __restrict__ beta,
    const float* __restrict__ mean,
    const float* __restrict__ var,
    const float* __restrict__ w2,      // (HID,)
    float* __restrict__ out)           // [OUT_ELEMS out][B*S*THW alpha]
{
    __shared__ u64 w1t2[80][32];       // {w,w} packed, permuted columns
    __shared__ u64 sc2[32], sh2[32];   // BN scale/shift packed, permuted
    __shared__ float w2s[32];

    const int tid = threadIdx.x;

    // ---- stage weights / BN params ----
    for (int idx = tid; idx < 80 * 32; idx += 128) {
        int k = idx >> 5, o = idx & 31;
        float w = w1[o * 80 + k];
        w1t2[k][pcol(o)] = pack2(w, w);
    }
    if (tid < 32) {
        int o = tid;
        float s  = gamma[o] / sqrtf(var[o] + 1e-5f);
        float sh = beta[o] - mean[o] * s;
        sc2[pcol(o)] = pack2(s, s);
        sh2[pcol(o)] = pack2(sh, sh);
        w2s[o] = w2[o];
    }
    __syncthreads();

    // ---- mapping: 4-lane group shares one pixel-pair, splits HID 4 ways ----
    const int  g     = tid & 3;                       // owns o in [g*8, g*8+8)
    const long gp    = (long)blockIdx.x * 32 + (tid >> 2);
    const long pix0  = gp * 2;                        // even -> 8B aligned
    const int  b     = (int)(pix0 >> 17);
    const int  thw   = (int)(pix0 & (THW - 1));

    const u64* fsp0 = (const u64*)(feats + (((long)(0 * 2 + b)) << 23) + thw);
    const u64* fsp1 = (const u64*)(feats + (((long)(1 * 2 + b)) << 23) + thw);
    const u64* fsp2 = (const u64*)(feats + (((long)(2 * 2 + b)) << 23) + thw);
    const u64* fsp3 = (const u64*)(feats + (((long)(3 * 2 + b)) << 23) + thw);

    // ---- p-part (same for all s) ----
    u64 acc[4][8];
#pragma unroll
    for (int i = 0; i < 8; i++) acc[0][i] = 0ULL;

    const u64* psp = (const u64*)(ps + (((long)b * NP) << 17) + thw);
#pragma unroll
    for (int p = 0; p < NP; p++) {
        u64 pv = psp[(long)p << 16];
#pragma unroll
        for (int i = 0; i < 8; i++)
            acc[0][i] = fma2(w1t2[64 + p][4 * i + g], pv, acc[0][i]);
    }
#pragma unroll
    for (int i = 0; i < 8; i++) { acc[1][i] = acc[0][i]; acc[2][i] = acc[0][i]; acc[3][i] = acc[0][i]; }

    // ---- main GEMV over f: one weight LDS feeds 4 FMA2 ----
#pragma unroll 4
    for (int f = 0; f < NF; f++) {
        u64 v0 = fsp0[(long)f << 16];
        u64 v1 = fsp1[(long)f << 16];
        u64 v2 = fsp2[(long)f << 16];
        u64 v3 = fsp3[(long)f << 16];
#pragma unroll
        for (int i = 0; i < 8; i++) {
            u64 w = w1t2[f][4 * i + g];
            acc[0][i] = fma2(w, v0, acc[0][i]);
            acc[1][i] = fma2(w, v1, acc[1][i]);
            acc[2][i] = fma2(w, v2, acc[2][i]);
            acc[3][i] = fma2(w, v3, acc[3][i]);
        }
    }

    // ---- BN + ReLU + logit dot, reduce across the 4-lane group ----
    float llo[4], lhi[4];
#pragma unroll
    for (int s = 0; s < 4; s++) {
        float alo = 0.f, ahi = 0.f;
#pragma unroll
        for (int i = 0; i < 8; i++) {
            u64 h = fma2(acc[s][i], sc2[4 * i + g], sh2[4 * i + g]);
            float x, y;
            unpack2(h, x, y);
            x = fmaxf(x, 0.f);
            y = fmaxf(y, 0.f);
            float wv = w2s[g * 8 + i];
            alo = fmaf(wv, x, alo);
            ahi = fmaf(wv, y, ahi);
        }
        alo += __shfl_xor_sync(0xffffffffu, alo, 1);
        ahi += __shfl_xor_sync(0xffffffffu, ahi, 1);
        alo += __shfl_xor_sync(0xffffffffu, alo, 2);
        ahi += __shfl_xor_sync(0xffffffffu, ahi, 2);
        llo[s] = alo;
        lhi[s] = ahi;
    }

    // ---- softmax over s (b2 constant -> cancels) ----
    float mlo = fmaxf(fmaxf(llo[0], llo[1]), fmaxf(llo[2], llo[3]));
    float mhi = fmaxf(fmaxf(lhi[0], lhi[1]), fmaxf(lhi[2], lhi[3]));
    float elo[4], ehi[4], zlo = 0.f, zhi = 0.f;
#pragma unroll
    for (int s = 0; s < 4; s++) {
        elo[s] = __expf(llo[s] - mlo);  zlo += elo[s];
        ehi[s] = __expf(lhi[s] - mhi);  zhi += ehi[s];
    }
    float rlo = 1.f / zlo, rhi = 1.f / zhi;
    u64 a2[4];
#pragma unroll
    for (int s = 0; s < 4; s++) a2[s] = pack2(elo[s] * rlo, ehi[s] * rhi);

    // ---- alpha output: (B,S,T,H,W); one lane of the group writes ----
    if (g == 0) {
        u64* ap = (u64*)(out + OUT_ELEMS + (((long)b * NS) << 17) + thw);
#pragma unroll
        for (int s = 0; s < 4; s++) ap[(long)s << 16] = a2[s];
    }

    // ---- pass 2: out[f] = sum_s alpha_s*feats[s,f]; group splits f (interleaved) ----
    u64* op = (u64*)(out + (((long)b) << 23) + thw);
#pragma unroll 4
    for (int j = 0; j < 16; j++) {
        const long fo = (long)(g + 4 * j) << 16;
        u64 v = mul2(a2[0], fsp0[fo]);
        v = fma2(a2[1], fsp1[fo], v);
        v = fma2(a2[2], fsp2[fo], v);
        v = fma2(a2[3], fsp3[fo], v);
        op[fo] = v;
    }
}

extern "C" void kernel_launch(void* const* d_in, const int* in_sizes, int n_in,
                              void* d_out, int out_size) {
    const float* feats = (const float*)d_in[0];
    const float* ps    = (const float*)d_in[1];
    const float* w1    = (const float*)d_in[2];
    const float* gamma = (const float*)d_in[3];
    const float* beta  = (const float*)d_in[4];
    const float* mean  = (const float*)d_in[5];
    const float* var   = (const float*)d_in[6];
    const float* w2    = (const float*)d_in[7];
    float* out = (float*)d_out;

    const int blocks = NPIX / 64;  // 4096: 128 threads = 32 pixel-pairs each
    gssm_kernel<<<blocks, 128>>>(feats, ps, w1, gamma, beta, mean, var, w2, out);
}